// round 2
// baseline (speedup 1.0000x reference)
#include <cuda_runtime.h>
#include <cstdint>

#define BATCH 8
#define NN    2048
#define CC    128
#define EPSV  0.1f

typedef unsigned long long ull;

// Scratch (static device globals — no runtime allocation)
__device__ float g_h[BATCH * NN * CC];   // 8.4 MB
__device__ float g_al[BATCH * NN];
__device__ float g_ar[BATCH * NN];

__device__ __forceinline__ ull pack2(float x, float y) {
    ull r; asm("mov.b64 %0, {%1, %2};" : "=l"(r) : "f"(x), "f"(y)); return r;
}
__device__ __forceinline__ float2 unpack2(ull v) {
    float2 r; asm("mov.b64 {%0, %1}, %2;" : "=f"(r.x), "=f"(r.y) : "l"(v)); return r;
}
// packed dual-fp32 FMA (sm_100+): d = a*b + c on both lanes
__device__ __forceinline__ ull fma2(ull a, ull b, ull c) {
    ull d; asm("fma.rn.f32x2 %0, %1, %2, %3;" : "=l"(d) : "l"(a), "l"(b), "l"(c)); return d;
}
__device__ __forceinline__ float tanh_fast(float x) {
    float y; asm("tanh.approx.f32 %0, %1;" : "=f"(y) : "f"(x)); return y;
}

// ---------------------------------------------------------------------------
// Kernel 1: h = x @ W  (16384 x 128 rows, K=128).
// Block: 128 thr, 32-row tile, full 128 cols. Thread = 2 rows x 16 cols.
// W staged in 32-k chunks as 16B vectors; x pre-packed (v,v) f32x2 in smem.
// Per k: 16 FFMA2 + 4 LDS.128 + 2 LDS.64.
// ---------------------------------------------------------------------------
__global__ void __launch_bounds__(128, 4)
prep_kernel(const float* __restrict__ x, const float* __restrict__ W) {
    __shared__ __align__(16) ulonglong2 sW2[32 * 32];  // [k][col/4] 16 KB
    __shared__ ull sX[32 * 33];                        // packed x [row][k], padded

    const int tid = threadIdx.x;
    const int tx  = tid & 7;          // col group: cols = q*32 + tx*4
    const int ty  = tid >> 3;         // 0..15 -> rows 2ty, 2ty+1
    const int row0 = blockIdx.x * 32;
    const int kb  = tid & 31;         // build: k index
    const int ig  = tid >> 5;         // build: row group (8 rows each)

    ull acc[2][8];
#pragma unroll
    for (int r = 0; r < 2; r++)
#pragma unroll
        for (int c = 0; c < 8; c++) acc[r][c] = 0ull;

    for (int kc = 0; kc < 4; kc++) {
        __syncthreads();
        // stage W chunk [32 k][128 cols]
        const float4* Wg = (const float4*)(W + (size_t)kc * 32 * CC);
        float4* sWf = (float4*)sW2;
#pragma unroll
        for (int q = 0; q < 8; q++) sWf[q * 128 + tid] = Wg[q * 128 + tid];
        // build packed x: rows ig*8+q, k = kb  (coalesced 128B per warp)
#pragma unroll
        for (int q = 0; q < 8; q++) {
            const int r = ig * 8 + q;
            const float v = x[(size_t)(row0 + r) * CC + kc * 32 + kb];
            sX[r * 33 + kb] = pack2(v, v);
        }
        __syncthreads();

#pragma unroll
        for (int kk = 0; kk < 32; kk++) {
            const ull a0 = sX[(2 * ty)     * 33 + kk];
            const ull a1 = sX[(2 * ty + 1) * 33 + kk];
#pragma unroll
            for (int q = 0; q < 4; q++) {
                const ulonglong2 wv = sW2[kk * 32 + q * 8 + tx];
                acc[0][2 * q]     = fma2(a0, wv.x, acc[0][2 * q]);
                acc[0][2 * q + 1] = fma2(a0, wv.y, acc[0][2 * q + 1]);
                acc[1][2 * q]     = fma2(a1, wv.x, acc[1][2 * q]);
                acc[1][2 * q + 1] = fma2(a1, wv.y, acc[1][2 * q + 1]);
            }
        }
    }

#pragma unroll
    for (int r = 0; r < 2; r++) {
        const size_t rowbase = (size_t)(row0 + 2 * ty + r) * CC;
#pragma unroll
        for (int q = 0; q < 4; q++) {
            const float2 p0 = unpack2(acc[r][2 * q]);
            const float2 p1 = unpack2(acc[r][2 * q + 1]);
            float4 o; o.x = p0.x; o.y = p0.y; o.z = p1.x; o.w = p1.y;
            *(float4*)&g_h[rowbase + q * 32 + tx * 4] = o;
        }
    }
}

// ---------------------------------------------------------------------------
// Kernel 2: alpha_l/r row dots. One warp per row.
// ---------------------------------------------------------------------------
__global__ void attred_kernel(const float* __restrict__ wl,
                              const float* __restrict__ wr) {
    const int gtid = blockIdx.x * blockDim.x + threadIdx.x;
    const int warp = gtid >> 5;
    const int lane = gtid & 31;
    const float4 hv  = *(const float4*)&g_h[(size_t)warp * CC + lane * 4];
    const float4 wlv = *(const float4*)&wl[lane * 4];
    const float4 wrv = *(const float4*)&wr[lane * 4];
    float pl = hv.x * wlv.x + hv.y * wlv.y + hv.z * wlv.z + hv.w * wlv.w;
    float pr = hv.x * wrv.x + hv.y * wrv.y + hv.z * wrv.z + hv.w * wrv.w;
#pragma unroll
    for (int off = 16; off; off >>= 1) {
        pl += __shfl_down_sync(0xffffffffu, pl, off);
        pr += __shfl_down_sync(0xffffffffu, pr, off);
    }
    if (lane == 0) { g_al[warp] = pl; g_ar[warp] = pr; }
}

// ---------------------------------------------------------------------------
// Kernel 3 (fused main): block = 32 i-rows x 128 cols for one batch.
// Per 32-j tile: build packed masked-tanh alpha (f32x2 (t,t)) + stage h tile,
// then MAC: per jj = 16 FFMA2 + 4 LDS.128 + 2 LDS.64  (FMA-pipe bound).
// ---------------------------------------------------------------------------
__global__ void __launch_bounds__(128, 4)
fagcn_main(const int* __restrict__ adj, const float* __restrict__ x0,
           float* __restrict__ out) {
    __shared__ __align__(16) ulonglong2 sH2[32 * 32];  // h tile [jj][col/4] 16 KB
    __shared__ ull sA[32 * 33];                        // packed (t,t) [i][jj], padded

    const int tid = threadIdx.x;
    const int tx  = tid & 7;         // col group
    const int ty  = tid >> 3;        // 0..15 -> rows 2ty, 2ty+1
    const int b   = blockIdx.x >> 6;
    const int i0  = (blockIdx.x & 63) * 32;
    const int jjb = tid & 31;        // build: jj
    const int ig  = tid >> 5;        // build: row group (8 rows each)

    const float* hb   = g_h + (size_t)b * NN * CC;
    const int*   adjb = adj + (size_t)(b * NN + i0) * NN;
    const float* alb  = g_al + b * NN;

    // build rows' alpha_r, hoisted (rows ig*8+q)
    float arv[8];
#pragma unroll
    for (int q = 0; q < 8; q++) arv[q] = g_ar[b * NN + i0 + ig * 8 + q];

    ull acc[2][8];
#pragma unroll
    for (int r = 0; r < 2; r++)
#pragma unroll
        for (int c = 0; c < 8; c++) acc[r][c] = 0ull;

    for (int jt = 0; jt < 64; jt++) {
        const int j0 = jt * 32;
        __syncthreads();
        // stage h tile: 32 rows x 128 floats = 1024 float4
        const float4* hsrc = (const float4*)(hb + (size_t)j0 * CC);
        float4* hdst = (float4*)sH2;
#pragma unroll
        for (int q = 0; q < 8; q++) hdst[q * 128 + tid] = hsrc[q * 128 + tid];

        // build packed masked alpha: thread -> jj=jjb, rows ig*8+q
        const float alv = alb[j0 + jjb];
#pragma unroll
        for (int q = 0; q < 8; q++) {
            const int i = ig * 8 + q;
            const int av = adjb[(size_t)i * NN + j0 + jjb];   // coalesced 128B
            const float t = av ? tanh_fast(arv[q] * alv) : 0.0f;
            sA[i * 33 + jjb] = pack2(t, t);
        }
        __syncthreads();

#pragma unroll
        for (int jj = 0; jj < 32; jj++) {
            const ull a0 = sA[(2 * ty)     * 33 + jj];  // LDS.64, conflict-free
            const ull a1 = sA[(2 * ty + 1) * 33 + jj];
#pragma unroll
            for (int q = 0; q < 4; q++) {
                const ulonglong2 hv = sH2[jj * 32 + q * 8 + tx];  // LDS.128, 128B contig
                acc[0][2 * q]     = fma2(a0, hv.x, acc[0][2 * q]);
                acc[0][2 * q + 1] = fma2(a0, hv.y, acc[0][2 * q + 1]);
                acc[1][2 * q]     = fma2(a1, hv.x, acc[1][2 * q]);
                acc[1][2 * q + 1] = fma2(a1, hv.y, acc[1][2 * q + 1]);
            }
        }
    }

    // epilogue: out = acc + EPS * x_0
#pragma unroll
    for (int r = 0; r < 2; r++) {
        const size_t rowbase = (size_t)(b * NN + i0 + 2 * ty + r) * CC;
#pragma unroll
        for (int q = 0; q < 4; q++) {
            const size_t idx = rowbase + q * 32 + tx * 4;
            const float4 xv = *(const float4*)&x0[idx];
            const float2 p0 = unpack2(acc[r][2 * q]);
            const float2 p1 = unpack2(acc[r][2 * q + 1]);
            float4 o;
            o.x = p0.x + EPSV * xv.x;
            o.y = p0.y + EPSV * xv.y;
            o.z = p1.x + EPSV * xv.z;
            o.w = p1.y + EPSV * xv.w;
            *(float4*)&out[idx] = o;
        }
    }
}

extern "C" void kernel_launch(void* const* d_in, const int* in_sizes, int n_in,
                              void* d_out, int out_size) {
    const float* x   = (const float*)d_in[0];
    const float* x0  = (const float*)d_in[1];
    const int*   adj = (const int*)d_in[2];
    const float* W   = (const float*)d_in[3];
    const float* wl  = (const float*)d_in[4];
    const float* wr  = (const float*)d_in[5];
    float* out = (float*)d_out;

    prep_kernel<<<BATCH * NN / 32, 128>>>(x, W);
    attred_kernel<<<BATCH * NN / 8, 256>>>(wl, wr);
    fagcn_main<<<BATCH * (NN / 32), 128>>>(adj, x0, out);
}

// round 4
// speedup vs baseline: 3.3653x; 3.3653x over previous
#include <cuda_runtime.h>
#include <cstdint>

#define BATCH 8
#define NN    2048
#define CC    128
#define EPSV  0.1f

typedef unsigned long long ull;

// Scratch (static device globals — no runtime allocation)
__device__ float g_h [BATCH * NN * CC];   // h [b][j][o]  fp32
__device__ float g_al[BATCH * NN];
__device__ float g_ar[BATCH * NN];

// ---------------------------------------------------------------- helpers --
__device__ __forceinline__ ull pack2(float x, float y) {
    ull r; asm("mov.b64 %0, {%1, %2};" : "=l"(r) : "f"(x), "f"(y)); return r;
}
__device__ __forceinline__ float2 unpack2(ull v) {
    float2 r; asm("mov.b64 {%0, %1}, %2;" : "=f"(r.x), "=f"(r.y) : "l"(v)); return r;
}
__device__ __forceinline__ ull fma2(ull a, ull b, ull c) {
    ull d; asm("fma.rn.f32x2 %0, %1, %2, %3;" : "=l"(d) : "l"(a), "l"(b), "l"(c)); return d;
}
__device__ __forceinline__ float tanh_fast(float x) {
    float y; asm("tanh.approx.f32 %0, %1;" : "=f"(y) : "f"(x)); return y;
}
__device__ __forceinline__ float cvt_tf32(float x) {
    uint32_t u; asm("cvt.rna.tf32.f32 %0, %1;" : "=r"(u) : "f"(x));
    return __uint_as_float(u);
}

// tf32 MMA m16n8k8: D(16x8) += A(16x8 row) * B(8x8 col); fp32 accum
__device__ __forceinline__ void mma_tf32(float* d, const uint32_t* a, const uint32_t* bfr) {
    asm volatile(
        "mma.sync.aligned.m16n8k8.row.col.f32.tf32.tf32.f32 "
        "{%0,%1,%2,%3}, {%4,%5,%6,%7}, {%8,%9}, {%0,%1,%2,%3};"
        : "+f"(d[0]), "+f"(d[1]), "+f"(d[2]), "+f"(d[3])
        : "r"(a[0]), "r"(a[1]), "r"(a[2]), "r"(a[3]), "r"(bfr[0]), "r"(bfr[1]));
}

// ---------------------------------------------------------------------------
// Kernel 1: h = x @ W  (scalar f32x2, measured 26.5us)
// ---------------------------------------------------------------------------
__global__ void __launch_bounds__(128, 4)
prep_kernel(const float* __restrict__ x, const float* __restrict__ W) {
    __shared__ __align__(16) ulonglong2 sW2[32 * 32];
    __shared__ ull sX[32 * 33];

    const int tid = threadIdx.x;
    const int tx  = tid & 7;
    const int ty  = tid >> 3;
    const int row0 = blockIdx.x * 32;
    const int kb  = tid & 31;
    const int ig  = tid >> 5;

    ull acc[2][8];
#pragma unroll
    for (int r = 0; r < 2; r++)
#pragma unroll
        for (int c = 0; c < 8; c++) acc[r][c] = 0ull;

    for (int kc = 0; kc < 4; kc++) {
        __syncthreads();
        const float4* Wg = (const float4*)(W + (size_t)kc * 32 * CC);
        float4* sWf = (float4*)sW2;
#pragma unroll
        for (int q = 0; q < 8; q++) sWf[q * 128 + tid] = Wg[q * 128 + tid];
#pragma unroll
        for (int q = 0; q < 8; q++) {
            const int r = ig * 8 + q;
            const float v = x[(size_t)(row0 + r) * CC + kc * 32 + kb];
            sX[r * 33 + kb] = pack2(v, v);
        }
        __syncthreads();
#pragma unroll
        for (int kk = 0; kk < 32; kk++) {
            const ull a0 = sX[(2 * ty)     * 33 + kk];
            const ull a1 = sX[(2 * ty + 1) * 33 + kk];
#pragma unroll
            for (int q = 0; q < 4; q++) {
                const ulonglong2 wv = sW2[kk * 32 + q * 8 + tx];
                acc[0][2 * q]     = fma2(a0, wv.x, acc[0][2 * q]);
                acc[0][2 * q + 1] = fma2(a0, wv.y, acc[0][2 * q + 1]);
                acc[1][2 * q]     = fma2(a1, wv.x, acc[1][2 * q]);
                acc[1][2 * q + 1] = fma2(a1, wv.y, acc[1][2 * q + 1]);
            }
        }
    }
#pragma unroll
    for (int r = 0; r < 2; r++) {
        const size_t rowbase = (size_t)(row0 + 2 * ty + r) * CC;
#pragma unroll
        for (int q = 0; q < 4; q++) {
            const float2 p0 = unpack2(acc[r][2 * q]);
            const float2 p1 = unpack2(acc[r][2 * q + 1]);
            float4 o; o.x = p0.x; o.y = p0.y; o.z = p1.x; o.w = p1.y;
            *(float4*)&g_h[rowbase + q * 32 + tx * 4] = o;
        }
    }
}

// ---------------------------------------------------------------------------
// Kernel 2: alpha_l/r row dots. One warp per row.
// ---------------------------------------------------------------------------
__global__ void attred_kernel(const float* __restrict__ wl,
                              const float* __restrict__ wr) {
    const int gtid = blockIdx.x * blockDim.x + threadIdx.x;
    const int warp = gtid >> 5;
    const int lane = gtid & 31;
    const float4 hv  = *(const float4*)&g_h[(size_t)warp * CC + lane * 4];
    const float4 wlv = *(const float4*)&wl[lane * 4];
    const float4 wrv = *(const float4*)&wr[lane * 4];
    float pl = hv.x * wlv.x + hv.y * wlv.y + hv.z * wlv.z + hv.w * wlv.w;
    float pr = hv.x * wrv.x + hv.y * wrv.y + hv.z * wrv.z + hv.w * wrv.w;
#pragma unroll
    for (int off = 16; off; off >>= 1) {
        pl += __shfl_down_sync(0xffffffffu, pl, off);
        pr += __shfl_down_sync(0xffffffffu, pr, off);
    }
    if (lane == 0) { g_al[warp] = pl; g_ar[warp] = pr; }
}

// ---------------------------------------------------------------------------
// Kernel 3 (main): mma.sync tf32. CTA = 128 i x 128 o, K=2048 (j), 8 warps.
// Warp tile 32i x 64o. Double-buffered smem; LDG prefetch overlaps MMA.
// ---------------------------------------------------------------------------
#define SA_STRIDE 36                 // 32 j-cols + pad (conflict-free frags)
#define SB_STRIDE 136                // 128 o-cols + pad
#define SA_TILE   (128 * SA_STRIDE)  // floats
#define SB_TILE   (32 * SB_STRIDE)
#define SM_FLOATS (2 * SA_TILE + 2 * SB_TILE + NN + 128)   // 20096 -> 80384 B

__global__ void __launch_bounds__(256, 1)
fagcn_main(const int* __restrict__ adj, const float* __restrict__ x0,
           float* __restrict__ out) {
    extern __shared__ __align__(16) float smem[];
    float* sA  = smem;                         // [2][128][36]
    float* sB  = smem + 2 * SA_TILE;           // [2][32][136]
    float* sAl = sB + 2 * SB_TILE;             // [2048]
    float* sAr = sAl + NN;                     // [128]

    const int tid  = threadIdx.x;
    const int w    = tid >> 5;
    const int lane = tid & 31;
    const int b    = blockIdx.x >> 4;
    const int i0   = (blockIdx.x & 15) * 128;

    const float* hb = g_h + (size_t)b * NN * CC;

    // stage alpha_l (2048) and alpha_r (128 rows of this i-tile)
    for (int i = tid; i < NN; i += 256) sAl[i] = g_al[b * NN + i];
    if (tid < 128) sAr[tid] = g_ar[b * NN + i0 + tid];
    __syncthreads();

    // ---- build mappings ----
    // A build: thread -> jcol=(tid&7)*4, rows ia_q = q*32 + (tid>>3)
    const int jcol = (tid & 7) * 4;
    const int ibase = tid >> 3;
    // B build: thread -> ocol=(tid&31)*4, rows jb_q = q*8 + (tid>>5)
    const int ocol = (tid & 31) * 4;
    const int jbase = tid >> 5;

    const int* adjp[4];
    float arv[4];
#pragma unroll
    for (int q = 0; q < 4; q++) {
        const int ia = q * 32 + ibase;
        adjp[q] = adj + ((size_t)(b * NN + i0 + ia)) * NN + jcol;
        arv[q] = sAr[ia];
    }

    // ---- MMA fragment indexing (warp tile: rows (w&3)*32, cols (w>>2)*64) ----
    const int wib = (w & 3) * 32;
    const int wob = (w >> 2) * 64;
    const int fr = lane >> 2;        // 0..7
    const int fc = lane & 3;         // 0..3

    float acc[2][8][4];
#pragma unroll
    for (int mt = 0; mt < 2; mt++)
#pragma unroll
        for (int nt = 0; nt < 8; nt++)
#pragma unroll
            for (int r = 0; r < 4; r++) acc[mt][nt][r] = 0.0f;

    int4   padj[4];
    float4 phv[4];

    // ---- initial build: tile 0 into buffer 0 ----
#pragma unroll
    for (int q = 0; q < 4; q++) padj[q] = *(const int4*)adjp[q];
#pragma unroll
    for (int q = 0; q < 4; q++)
        phv[q] = *(const float4*)&hb[(size_t)(q * 8 + jbase) * CC + ocol];
#pragma unroll
    for (int q = 0; q < 4; q++) {
        const float4 al4 = *(const float4*)&sAl[jcol];
        float4 t;
        t.x = cvt_tf32(padj[q].x ? tanh_fast(arv[q] * al4.x) : 0.0f);
        t.y = cvt_tf32(padj[q].y ? tanh_fast(arv[q] * al4.y) : 0.0f);
        t.z = cvt_tf32(padj[q].z ? tanh_fast(arv[q] * al4.z) : 0.0f);
        t.w = cvt_tf32(padj[q].w ? tanh_fast(arv[q] * al4.w) : 0.0f);
        *(float4*)&sA[(q * 32 + ibase) * SA_STRIDE + jcol] = t;
    }
#pragma unroll
    for (int q = 0; q < 4; q++) {
        float4 v = phv[q];
        v.x = cvt_tf32(v.x); v.y = cvt_tf32(v.y);
        v.z = cvt_tf32(v.z); v.w = cvt_tf32(v.w);
        *(float4*)&sB[(q * 8 + jbase) * SB_STRIDE + ocol] = v;
    }
    __syncthreads();

    for (int kt = 0; kt < 64; kt++) {
        const int s = kt & 1;
        const int j0n = (kt + 1) * 32;

        // prefetch next tile (LDGs in flight during MMA)
        if (kt < 63) {
#pragma unroll
            for (int q = 0; q < 4; q++) padj[q] = *(const int4*)(adjp[q] + j0n);
#pragma unroll
            for (int q = 0; q < 4; q++)
                phv[q] = *(const float4*)&hb[(size_t)(j0n + q * 8 + jbase) * CC + ocol];
        }

        // ---- MMA over buffer s ----
        {
            const float* A = sA + s * SA_TILE + (size_t)wib * SA_STRIDE;
            const float* B = sB + s * SB_TILE + wob;
#pragma unroll
            for (int ks = 0; ks < 4; ks++) {
                uint32_t af[2][4];
#pragma unroll
                for (int mt = 0; mt < 2; mt++) {
                    const float* Ab = A + (mt * 16 + fr) * SA_STRIDE + ks * 8 + fc;
                    af[mt][0] = __float_as_uint(Ab[0]);
                    af[mt][1] = __float_as_uint(Ab[8 * SA_STRIDE]);
                    af[mt][2] = __float_as_uint(Ab[4]);
                    af[mt][3] = __float_as_uint(Ab[8 * SA_STRIDE + 4]);
                }
                uint32_t bf[8][2];
#pragma unroll
                for (int nt = 0; nt < 8; nt++) {
                    const float* Bb = B + (ks * 8 + fc) * SB_STRIDE + nt * 8 + fr;
                    bf[nt][0] = __float_as_uint(Bb[0]);
                    bf[nt][1] = __float_as_uint(Bb[4 * SB_STRIDE]);
                }
#pragma unroll
                for (int mt = 0; mt < 2; mt++)
#pragma unroll
                    for (int nt = 0; nt < 8; nt++)
                        mma_tf32(acc[mt][nt], af[mt], bf[nt]);
            }
        }

        // ---- build next tile into buffer s^1 ----
        if (kt < 63) {
            float* An = sA + (s ^ 1) * SA_TILE;
            float* Bn = sB + (s ^ 1) * SB_TILE;
            const float4 al4 = *(const float4*)&sAl[j0n + jcol];
#pragma unroll
            for (int q = 0; q < 4; q++) {
                float4 t;
                t.x = cvt_tf32(padj[q].x ? tanh_fast(arv[q] * al4.x) : 0.0f);
                t.y = cvt_tf32(padj[q].y ? tanh_fast(arv[q] * al4.y) : 0.0f);
                t.z = cvt_tf32(padj[q].z ? tanh_fast(arv[q] * al4.z) : 0.0f);
                t.w = cvt_tf32(padj[q].w ? tanh_fast(arv[q] * al4.w) : 0.0f);
                *(float4*)&An[(q * 32 + ibase) * SA_STRIDE + jcol] = t;
            }
#pragma unroll
            for (int q = 0; q < 4; q++) {
                float4 v = phv[q];
                v.x = cvt_tf32(v.x); v.y = cvt_tf32(v.y);
                v.z = cvt_tf32(v.z); v.w = cvt_tf32(v.w);
                *(float4*)&Bn[(q * 8 + jbase) * SB_STRIDE + ocol] = v;
            }
        }
        __syncthreads();
    }

    // ---- epilogue: out = acc + EPS * x0 ----
#pragma unroll
    for (int mt = 0; mt < 2; mt++) {
        const int row = i0 + wib + mt * 16 + fr;
#pragma unroll
        for (int nt = 0; nt < 8; nt++) {
            const int col = wob + nt * 8 + fc * 2;
            const size_t base0 = ((size_t)(b * NN + row)) * CC + col;
            const size_t base1 = base0 + 8 * CC;
            const float2 x00 = *(const float2*)&x0[base0];
            const float2 x01 = *(const float2*)&x0[base1];
            float2 o0, o1;
            o0.x = acc[mt][nt][0] + EPSV * x00.x;
            o0.y = acc[mt][nt][1] + EPSV * x00.y;
            o1.x = acc[mt][nt][2] + EPSV * x01.x;
            o1.y = acc[mt][nt][3] + EPSV * x01.y;
            *(float2*)&out[base0] = o0;
            *(float2*)&out[base1] = o1;
        }
    }
}

extern "C" void kernel_launch(void* const* d_in, const int* in_sizes, int n_in,
                              void* d_out, int out_size) {
    const float* x   = (const float*)d_in[0];
    const float* x0  = (const float*)d_in[1];
    const int*   adj = (const int*)d_in[2];
    const float* W   = (const float*)d_in[3];
    const float* wl  = (const float*)d_in[4];
    const float* wr  = (const float*)d_in[5];
    float* out = (float*)d_out;

    static bool attr_set = false;
    if (!attr_set) {
        cudaFuncSetAttribute(fagcn_main, cudaFuncAttributeMaxDynamicSharedMemorySize,
                             SM_FLOATS * (int)sizeof(float));
        attr_set = true;
    }

    prep_kernel<<<BATCH * NN / 32, 128>>>(x, W);
    attred_kernel<<<BATCH * NN / 8, 256>>>(wl, wr);
    fagcn_main<<<BATCH * (NN / 128), 256, SM_FLOATS * (int)sizeof(float)>>>(adj, x0, out);
}

// round 6
// speedup vs baseline: 4.5570x; 1.3541x over previous
#include <cuda_runtime.h>
#include <cuda_fp16.h>
#include <cstdint>

#define BATCH 8
#define NN    2048
#define CC    128
#define EPSV  0.1f

// Scratch (static device globals — no runtime allocation)
__device__ __half g_WT[CC * CC];                  // W^T [o][k] fp16
__device__ __half g_hT[BATCH * 64 * CC * 32];     // blocked hT [b][kt][o][jj] fp16
__device__ float  g_al[BATCH * NN];
__device__ float  g_ar[BATCH * NN];

// ---------------------------------------------------------------- helpers --
__device__ __forceinline__ float tanh_fast(float x) {
    float y; asm("tanh.approx.f32 %0, %1;" : "=f"(y) : "f"(x)); return y;
}
__device__ __forceinline__ uint32_t f2h2(float lo, float hi) {
    __half2 h = __floats2half2_rn(lo, hi);
    return *(uint32_t*)&h;
}
// fp16 MMA m16n8k16: D(16x8,f32) += A(16x16 row,f16) * B(16x8 col,f16)
__device__ __forceinline__ void mma_f16(float* d, const uint32_t* a, uint32_t b0, uint32_t b1) {
    asm volatile(
        "mma.sync.aligned.m16n8k16.row.col.f32.f16.f16.f32 "
        "{%0,%1,%2,%3}, {%4,%5,%6,%7}, {%8,%9}, {%0,%1,%2,%3};"
        : "+f"(d[0]), "+f"(d[1]), "+f"(d[2]), "+f"(d[3])
        : "r"(a[0]), "r"(a[1]), "r"(a[2]), "r"(a[3]), "r"(b0), "r"(b1));
}

// ---------------------------------------------------------------------------
// Kernel 0: W [k][o] fp32 -> g_WT [o][k] fp16.  grid 4 x 256.
// ---------------------------------------------------------------------------
__global__ void convW_kernel(const float* __restrict__ W) {
    const int t  = blockIdx.x * 256 + threadIdx.x;   // 0..1023
    const int o  = t >> 3;
    const int kc = (t & 7) * 16;
    uint32_t w[8];
#pragma unroll
    for (int q = 0; q < 8; q++) {
        const float a = W[(size_t)(kc + 2 * q)     * CC + o];
        const float b = W[(size_t)(kc + 2 * q + 1) * CC + o];
        w[q] = f2h2(a, b);
    }
    uint4* dst = (uint4*)(g_WT + (size_t)o * CC + kc);
    dst[0] = make_uint4(w[0], w[1], w[2], w[3]);
    dst[1] = make_uint4(w[4], w[5], w[6], w[7]);
}

// ---------------------------------------------------------------------------
// Kernel 1 (prep): h = x @ W via fp16 mma; epilogue computes alpha_l/alpha_r
// AND stores h as blocked fp16 hT [b][kt][o][jj].  One block = 128 rows.
// smem word stride 68 per 128-half row (conflict-free frags).
// ---------------------------------------------------------------------------
#define PX_W 68
#define PREP_SMEM_BYTES ((2 * 128 * PX_W + 256) * 4)

__global__ void __launch_bounds__(256, 1)
prep_tensor(const float* __restrict__ x, const float* __restrict__ wl,
            const float* __restrict__ wr) {
    extern __shared__ __align__(16) uint32_t sm[];
    uint32_t* sX  = sm;                        // [128][68] words (x fp16, then h fp16)
    uint32_t* sW  = sm + 128 * PX_W;           // [128 o][68] words (W^T fp16)
    float*    swl = (float*)(sm + 2 * 128 * PX_W);
    float*    swr = swl + 128;

    const int tid  = threadIdx.x;
    const int w    = tid >> 5;
    const int lane = tid & 31;
    const int fr   = lane >> 2;
    const int fc   = lane & 3;
    const int b    = blockIdx.x >> 4;
    const int j0   = (blockIdx.x & 15) * 128;
    const int r0   = blockIdx.x * 128;         // == b*NN + j0

    if (tid < 128) { swl[tid] = wl[tid]; swr[tid] = wr[tid]; }

    // stage x tile [128][128] fp32 -> fp16
#pragma unroll
    for (int e = 0; e < 16; e++) {
        const int idx = e * 256 + tid;
        const int row = idx >> 5;
        const int c4  = (idx & 31) * 4;
        const float4 v = *(const float4*)&x[(size_t)(r0 + row) * CC + c4];
        uint2 p; p.x = f2h2(v.x, v.y); p.y = f2h2(v.z, v.w);
        *(uint2*)&sX[row * PX_W + (idx & 31) * 2] = p;
    }
    // stage W^T [128 o][128 k] fp16: 2048 uint4 total  (FIX: was e<4 / half of W)
#pragma unroll
    for (int e = 0; e < 8; e++) {
        const int idx = e * 256 + tid;          // 0..2047
        const int o   = idx >> 4;
        const int ks  = idx & 15;
        const uint4 v = ((const uint4*)g_WT)[idx];
        *(uint4*)&sW[o * PX_W + ks * 4] = v;
    }
    __syncthreads();

    // MMA: warp rows wib = w*16, cols all 128 (nt 0..15)
    const int wib = w * 16;
    float acc[16][4];
#pragma unroll
    for (int nt = 0; nt < 16; nt++)
#pragma unroll
        for (int c = 0; c < 4; c++) acc[nt][c] = 0.0f;

#pragma unroll
    for (int ks = 0; ks < 8; ks++) {
        uint32_t af[4];
        const int abase = (wib + fr) * PX_W + ks * 8 + fc;
        af[0] = sX[abase];
        af[1] = sX[abase + 8 * PX_W];
        af[2] = sX[abase + 4];
        af[3] = sX[abase + 8 * PX_W + 4];
#pragma unroll
        for (int nt = 0; nt < 16; nt++) {
            const int bbase = (nt * 8 + fr) * PX_W + ks * 8 + fc;
            mma_f16(acc[nt], af, sW[bbase], sW[bbase + 4]);
        }
    }
    __syncthreads();

    // dump h (fp16) into sX region: [row j][o], stride 68 words
#pragma unroll
    for (int nt = 0; nt < 16; nt++) {
        sX[(wib + fr)     * PX_W + nt * 4 + fc] = f2h2(acc[nt][0], acc[nt][1]);
        sX[(wib + fr + 8) * PX_W + nt * 4 + fc] = f2h2(acc[nt][2], acc[nt][3]);
    }
    __syncthreads();

    const __half* sH = (const __half*)sX;       // [j][o] stride 136 halfs

    // blocked hT store: thread -> o = tid>>1, jh = tid&1 (64 j each)
    {
        const int o  = tid >> 1;
        const int jh = tid & 1;
        uint32_t wbuf[32];
#pragma unroll
        for (int r2 = 0; r2 < 32; r2++) {
            const int j = jh * 64 + r2 * 2;
            const __half h0 = sH[(size_t)j * 136 + o];
            const __half h1 = sH[(size_t)(j + 1) * 136 + o];
            wbuf[r2] = (uint32_t)__half_as_ushort(h0) | ((uint32_t)__half_as_ushort(h1) << 16);
        }
#pragma unroll
        for (int s = 0; s < 2; s++) {
            const int kt = (j0 >> 5) + jh * 2 + s;
            uint4* dst = (uint4*)(g_hT + ((size_t)((b * 64 + kt) * 128 + o)) * 32);
            const uint32_t* src = wbuf + s * 16;
            dst[0] = make_uint4(src[0],  src[1],  src[2],  src[3]);
            dst[1] = make_uint4(src[4],  src[5],  src[6],  src[7]);
            dst[2] = make_uint4(src[8],  src[9],  src[10], src[11]);
            dst[3] = make_uint4(src[12], src[13], src[14], src[15]);
        }
    }

    // alpha_l / alpha_r dots: thread -> r = tid>>1, oh = tid&1 (64 cols each)
    {
        const int r  = tid >> 1;
        const int oh = tid & 1;
        float pl = 0.0f, pr = 0.0f;
#pragma unroll
        for (int w2 = 0; w2 < 32; w2++) {
            const uint32_t wd = ((const uint32_t*)sH)[r * PX_W + oh * 32 + w2];
            const __half2 hh = *(const __half2*)&wd;
            const float2 f = __half22float2(hh);
            const int o0 = oh * 64 + w2 * 2;
            pl += f.x * swl[o0] + f.y * swl[o0 + 1];
            pr += f.x * swr[o0] + f.y * swr[o0 + 1];
        }
        pl += __shfl_xor_sync(0xffffffffu, pl, 1);
        pr += __shfl_xor_sync(0xffffffffu, pr, 1);
        if (oh == 0) {
            g_al[b * NN + j0 + r] = pl;
            g_ar[b * NN + j0 + r] = pr;
        }
    }
}

// ---------------------------------------------------------------------------
// Kernel 2 (main): fp16 mma. CTA = 128 i x 128 o, K=2048 (j), 8 warps.
// Warp tile 32i x 64o. Double-buffered smem; LDG prefetch overlaps MMA.
// ---------------------------------------------------------------------------
#define SA_W 20                         // words per 32-half row (+pad)
#define SB_W 20
#define SA_TILE_W (128 * SA_W)          // 2560 words
#define SB_TILE_W (128 * SB_W)
#define MAIN_SMEM_WORDS (2 * SA_TILE_W + 2 * SB_TILE_W + NN + 128)
#define MAIN_SMEM_BYTES (MAIN_SMEM_WORDS * 4)

__global__ void __launch_bounds__(256, 1)
fagcn_main(const int* __restrict__ adj, const float* __restrict__ x0,
           float* __restrict__ out) {
    extern __shared__ __align__(16) uint32_t smw[];
    uint32_t* sA  = smw;                          // [2][128 i][20]
    uint32_t* sB  = smw + 2 * SA_TILE_W;          // [2][128 o][20]
    float*    sAl = (float*)(smw + 2 * SA_TILE_W + 2 * SB_TILE_W);
    float*    sAr = sAl + NN;

    const int tid  = threadIdx.x;
    const int w    = tid >> 5;
    const int lane = tid & 31;
    const int fr   = lane >> 2;
    const int fc   = lane & 3;
    const int b    = blockIdx.x >> 4;
    const int i0   = (blockIdx.x & 15) * 128;

    // stage alpha_l (2048) and alpha_r (128)
    for (int i = tid; i < NN; i += 256) sAl[i] = g_al[b * NN + i];
    if (tid < 128) sAr[tid] = g_ar[b * NN + i0 + tid];
    __syncthreads();

    // A build mapping: jcol=(tid&7)*4, rows q*32 + (tid>>3)
    const int jcol  = (tid & 7) * 4;
    const int ibase = tid >> 3;
    const int* adjp[4];
    float arv[4];
#pragma unroll
    for (int q = 0; q < 4; q++) {
        const int ia = q * 32 + ibase;
        adjp[q] = adj + ((size_t)(b * NN + i0 + ia)) * NN + jcol;
        arv[q] = sAr[ia];
    }
    // B build src base (blocked hT for this batch)
    const uint4* hTb = (const uint4*)(g_hT + ((size_t)b * 64 * 128) * 32);

    // warp tile
    const int wib = (w & 3) * 32;
    const int wob = (w >> 2) * 64;

    float acc[2][8][4];
#pragma unroll
    for (int mt = 0; mt < 2; mt++)
#pragma unroll
        for (int nt = 0; nt < 8; nt++)
#pragma unroll
            for (int c = 0; c < 4; c++) acc[mt][nt][c] = 0.0f;

    int4  padj[4];
    uint4 pB[2];

    // ---- prologue: fetch + build tile 0 into buffer 0 ----
#pragma unroll
    for (int q = 0; q < 4; q++) padj[q] = *(const int4*)adjp[q];
#pragma unroll
    for (int q = 0; q < 2; q++) pB[q] = hTb[(size_t)0 * 512 + q * 256 + tid];
    {
        const float4 al4 = *(const float4*)&sAl[jcol];
#pragma unroll
        for (int q = 0; q < 4; q++) {
            const float t0 = padj[q].x ? tanh_fast(arv[q] * al4.x) : 0.0f;
            const float t1 = padj[q].y ? tanh_fast(arv[q] * al4.y) : 0.0f;
            const float t2 = padj[q].z ? tanh_fast(arv[q] * al4.z) : 0.0f;
            const float t3 = padj[q].w ? tanh_fast(arv[q] * al4.w) : 0.0f;
            uint2 p; p.x = f2h2(t0, t1); p.y = f2h2(t2, t3);
            *(uint2*)&sA[(q * 32 + ibase) * SA_W + (tid & 7) * 2] = p;
        }
#pragma unroll
        for (int q = 0; q < 2; q++) {
            const int idx = q * 256 + tid;
            const int o   = idx >> 2;
            const int seg = idx & 3;
            *(uint4*)&sB[o * SB_W + seg * 4] = pB[q];
        }
    }
    __syncthreads();

    for (int kt = 0; kt < 64; kt++) {
        const int s = kt & 1;

        // prefetch next tile
        if (kt < 63) {
            const int j0n = (kt + 1) * 32;
#pragma unroll
            for (int q = 0; q < 4; q++) padj[q] = *(const int4*)(adjp[q] + j0n);
#pragma unroll
            for (int q = 0; q < 2; q++)
                pB[q] = hTb[(size_t)(kt + 1) * 512 + q * 256 + tid];
        }

        // ---- MMA over buffer s ----
        {
            const uint32_t* A = sA + s * SA_TILE_W + (size_t)wib * SA_W;
            const uint32_t* B = sB + s * SB_TILE_W + (size_t)wob * SB_W;
#pragma unroll
            for (int ks = 0; ks < 2; ks++) {
                uint32_t af[2][4];
#pragma unroll
                for (int mt = 0; mt < 2; mt++) {
                    const int abase = (mt * 16 + fr) * SA_W + ks * 8 + fc;
                    af[mt][0] = A[abase];
                    af[mt][1] = A[abase + 8 * SA_W];
                    af[mt][2] = A[abase + 4];
                    af[mt][3] = A[abase + 8 * SA_W + 4];
                }
#pragma unroll
                for (int nt = 0; nt < 8; nt++) {
                    const int bbase = (nt * 8 + fr) * SB_W + ks * 8 + fc;
                    const uint32_t b0 = B[bbase];
                    const uint32_t b1 = B[bbase + 4];
                    mma_f16(acc[0][nt], af[0], b0, b1);
                    mma_f16(acc[1][nt], af[1], b0, b1);
                }
            }
        }

        // ---- build next tile into buffer s^1 ----
        if (kt < 63) {
            const int j0n = (kt + 1) * 32;
            uint32_t* An = sA + (s ^ 1) * SA_TILE_W;
            uint32_t* Bn = sB + (s ^ 1) * SB_TILE_W;
            const float4 al4 = *(const float4*)&sAl[j0n + jcol];
#pragma unroll
            for (int q = 0; q < 4; q++) {
                const float t0 = padj[q].x ? tanh_fast(arv[q] * al4.x) : 0.0f;
                const float t1 = padj[q].y ? tanh_fast(arv[q] * al4.y) : 0.0f;
                const float t2 = padj[q].z ? tanh_fast(arv[q] * al4.z) : 0.0f;
                const float t3 = padj[q].w ? tanh_fast(arv[q] * al4.w) : 0.0f;
                uint2 p; p.x = f2h2(t0, t1); p.y = f2h2(t2, t3);
                *(uint2*)&An[(q * 32 + ibase) * SA_W + (tid & 7) * 2] = p;
            }
#pragma unroll
            for (int q = 0; q < 2; q++) {
                const int idx = q * 256 + tid;
                const int o   = idx >> 2;
                const int seg = idx & 3;
                *(uint4*)&Bn[o * SB_W + seg * 4] = pB[q];
            }
        }
        __syncthreads();
    }

    // ---- epilogue: out = acc + EPS * x0 ----
#pragma unroll
    for (int mt = 0; mt < 2; mt++) {
        const int row = i0 + wib + mt * 16 + fr;
#pragma unroll
        for (int nt = 0; nt < 8; nt++) {
            const int col = wob + nt * 8 + fc * 2;
            const size_t base0 = ((size_t)(b * NN + row)) * CC + col;
            const size_t base1 = base0 + 8 * CC;
            const float2 x00 = *(const float2*)&x0[base0];
            const float2 x01 = *(const float2*)&x0[base1];
            float2 o0, o1;
            o0.x = acc[mt][nt][0] + EPSV * x00.x;
            o0.y = acc[mt][nt][1] + EPSV * x00.y;
            o1.x = acc[mt][nt][2] + EPSV * x01.x;
            o1.y = acc[mt][nt][3] + EPSV * x01.y;
            *(float2*)&out[base0] = o0;
            *(float2*)&out[base1] = o1;
        }
    }
}

extern "C" void kernel_launch(void* const* d_in, const int* in_sizes, int n_in,
                              void* d_out, int out_size) {
    const float* x   = (const float*)d_in[0];
    const float* x0  = (const float*)d_in[1];
    const int*   adj = (const int*)d_in[2];
    const float* W   = (const float*)d_in[3];
    const float* wl  = (const float*)d_in[4];
    const float* wr  = (const float*)d_in[5];
    float* out = (float*)d_out;

    static bool attr_set = false;
    if (!attr_set) {
        cudaFuncSetAttribute(prep_tensor, cudaFuncAttributeMaxDynamicSharedMemorySize,
                             PREP_SMEM_BYTES);
        cudaFuncSetAttribute(fagcn_main, cudaFuncAttributeMaxDynamicSharedMemorySize,
                             MAIN_SMEM_BYTES);
        attr_set = true;
    }

    convW_kernel<<<4, 256>>>(W);
    prep_tensor<<<BATCH * (NN / 128), 256, PREP_SMEM_BYTES>>>(x, wl, wr);
    fagcn_main<<<BATCH * (NN / 128), 256, MAIN_SMEM_BYTES>>>(adj, x0, out);
}

// round 7
// speedup vs baseline: 5.0445x; 1.1070x over previous
#include <cuda_runtime.h>
#include <cuda_fp16.h>
#include <cstdint>

#define BATCH 8
#define NN    2048
#define CC    128
#define EPSV  0.1f

// Scratch (static device globals — no runtime allocation)
__device__ __half g_WT[CC * CC];                  // W^T [o][k] fp16
__device__ __half g_hT[BATCH * 64 * CC * 32];     // blocked hT [b][kt][o][jj] fp16
__device__ float  g_al[BATCH * NN];
__device__ float  g_ar[BATCH * NN];

// ---------------------------------------------------------------- helpers --
__device__ __forceinline__ float tanh_fast(float x) {
    float y; asm("tanh.approx.f32 %0, %1;" : "=f"(y) : "f"(x)); return y;
}
__device__ __forceinline__ uint32_t f2h2(float lo, float hi) {
    __half2 h = __floats2half2_rn(lo, hi);
    return *(uint32_t*)&h;
}
__device__ __forceinline__ uint32_t smem_u32(const void* p) {
    uint32_t a;
    asm("{ .reg .u64 t; cvta.to.shared.u64 t, %1; cvt.u32.u64 %0, t; }" : "=r"(a) : "l"(p));
    return a;
}
// fp16 MMA m16n8k16: D(16x8,f32) += A(16x16 row,f16) * B(16x8 col,f16)
__device__ __forceinline__ void mma_f16(float* d, const uint32_t* a, uint32_t b0, uint32_t b1) {
    asm volatile(
        "mma.sync.aligned.m16n8k16.row.col.f32.f16.f16.f32 "
        "{%0,%1,%2,%3}, {%4,%5,%6,%7}, {%8,%9}, {%0,%1,%2,%3};"
        : "+f"(d[0]), "+f"(d[1]), "+f"(d[2]), "+f"(d[3])
        : "r"(a[0]), "r"(a[1]), "r"(a[2]), "r"(a[3]), "r"(b0), "r"(b1));
}
__device__ __forceinline__ void ldmatrix_x4(uint32_t& r0, uint32_t& r1,
                                            uint32_t& r2, uint32_t& r3, uint32_t addr) {
    asm volatile("ldmatrix.sync.aligned.m8n8.x4.shared.b16 {%0,%1,%2,%3}, [%4];"
                 : "=r"(r0), "=r"(r1), "=r"(r2), "=r"(r3) : "r"(addr));
}

// ---------------------------------------------------------------------------
// Kernel 0: W [k][o] fp32 -> g_WT [o][k] fp16.  16 blocks x 256 thr (32x32 tiles).
// ---------------------------------------------------------------------------
__global__ void __launch_bounds__(256) convW_kernel(const float* __restrict__ W) {
    __shared__ float st[32][33];
    const int bx = blockIdx.x & 3;    // k tile
    const int by = blockIdx.x >> 2;   // o tile
    const int r  = threadIdx.x >> 3;
    const int c4 = (threadIdx.x & 7) * 4;

    const float4 v = *(const float4*)&W[(size_t)(bx * 32 + r) * CC + by * 32 + c4];
    st[r][c4 + 0] = v.x; st[r][c4 + 1] = v.y; st[r][c4 + 2] = v.z; st[r][c4 + 3] = v.w;
    __syncthreads();

    uint2 p;
    p.x = f2h2(st[c4 + 0][r], st[c4 + 1][r]);
    p.y = f2h2(st[c4 + 2][r], st[c4 + 3][r]);
    *(uint2*)&g_WT[(size_t)(by * 32 + r) * CC + bx * 32 + c4] = p;
}

// ---------------------------------------------------------------------------
// Kernel 1 (prep): h = x @ W via fp16 mma; epilogue computes alpha_l/alpha_r
// AND stores h as blocked fp16 hT [b][kt][o][jj].  One block = 128 rows.
// ---------------------------------------------------------------------------
#define PX_W 68
#define PREP_SMEM_BYTES ((2 * 128 * PX_W + 256) * 4)

__global__ void __launch_bounds__(256, 1)
prep_tensor(const float* __restrict__ x, const float* __restrict__ wl,
            const float* __restrict__ wr) {
    extern __shared__ __align__(16) uint32_t sm[];
    uint32_t* sX  = sm;                        // [128][68] words (x fp16, then h fp16)
    uint32_t* sW  = sm + 128 * PX_W;           // [128 o][68] words (W^T fp16)
    float*    swl = (float*)(sm + 2 * 128 * PX_W);
    float*    swr = swl + 128;

    const int tid  = threadIdx.x;
    const int w    = tid >> 5;
    const int lane = tid & 31;
    const int fr   = lane >> 2;
    const int fc   = lane & 3;
    const int b    = blockIdx.x >> 4;
    const int j0   = (blockIdx.x & 15) * 128;
    const int r0   = blockIdx.x * 128;

    if (tid < 128) { swl[tid] = wl[tid]; swr[tid] = wr[tid]; }

    // stage x tile [128][128] fp32 -> fp16
#pragma unroll
    for (int e = 0; e < 16; e++) {
        const int idx = e * 256 + tid;
        const int row = idx >> 5;
        const int c4  = (idx & 31) * 4;
        const float4 v = *(const float4*)&x[(size_t)(r0 + row) * CC + c4];
        uint2 p; p.x = f2h2(v.x, v.y); p.y = f2h2(v.z, v.w);
        *(uint2*)&sX[row * PX_W + (idx & 31) * 2] = p;
    }
    // stage W^T [128 o][128 k] fp16: 2048 uint4 total
#pragma unroll
    for (int e = 0; e < 8; e++) {
        const int idx = e * 256 + tid;
        const int o   = idx >> 4;
        const int ks  = idx & 15;
        const uint4 v = ((const uint4*)g_WT)[idx];
        *(uint4*)&sW[o * PX_W + ks * 4] = v;
    }
    __syncthreads();

    const int wib = w * 16;
    float acc[16][4];
#pragma unroll
    for (int nt = 0; nt < 16; nt++)
#pragma unroll
        for (int c = 0; c < 4; c++) acc[nt][c] = 0.0f;

#pragma unroll
    for (int ks = 0; ks < 8; ks++) {
        uint32_t af[4];
        const int abase = (wib + fr) * PX_W + ks * 8 + fc;
        af[0] = sX[abase];
        af[1] = sX[abase + 8 * PX_W];
        af[2] = sX[abase + 4];
        af[3] = sX[abase + 8 * PX_W + 4];
#pragma unroll
        for (int nt = 0; nt < 16; nt++) {
            const int bbase = (nt * 8 + fr) * PX_W + ks * 8 + fc;
            mma_f16(acc[nt], af, sW[bbase], sW[bbase + 4]);
        }
    }
    __syncthreads();

    // dump h (fp16) into sX region: [row j][o], stride 68 words
#pragma unroll
    for (int nt = 0; nt < 16; nt++) {
        sX[(wib + fr)     * PX_W + nt * 4 + fc] = f2h2(acc[nt][0], acc[nt][1]);
        sX[(wib + fr + 8) * PX_W + nt * 4 + fc] = f2h2(acc[nt][2], acc[nt][3]);
    }
    __syncthreads();

    const __half* sH = (const __half*)sX;       // [j][o] stride 136 halfs

    // blocked hT store: thread -> o = tid>>1, jh = tid&1 (64 j each)
    {
        const int o  = tid >> 1;
        const int jh = tid & 1;
        uint32_t wbuf[32];
#pragma unroll
        for (int r2 = 0; r2 < 32; r2++) {
            const int j = jh * 64 + r2 * 2;
            const __half h0 = sH[(size_t)j * 136 + o];
            const __half h1 = sH[(size_t)(j + 1) * 136 + o];
            wbuf[r2] = (uint32_t)__half_as_ushort(h0) | ((uint32_t)__half_as_ushort(h1) << 16);
        }
#pragma unroll
        for (int s = 0; s < 2; s++) {
            const int kt = (j0 >> 5) + jh * 2 + s;
            uint4* dst = (uint4*)(g_hT + ((size_t)((b * 64 + kt) * 128 + o)) * 32);
            const uint32_t* src = wbuf + s * 16;
            dst[0] = make_uint4(src[0],  src[1],  src[2],  src[3]);
            dst[1] = make_uint4(src[4],  src[5],  src[6],  src[7]);
            dst[2] = make_uint4(src[8],  src[9],  src[10], src[11]);
            dst[3] = make_uint4(src[12], src[13], src[14], src[15]);
        }
    }

    // alpha_l / alpha_r dots
    {
        const int r  = tid >> 1;
        const int oh = tid & 1;
        float pl = 0.0f, pr = 0.0f;
#pragma unroll
        for (int w2 = 0; w2 < 32; w2++) {
            const uint32_t wd = ((const uint32_t*)sH)[r * PX_W + oh * 32 + w2];
            const __half2 hh = *(const __half2*)&wd;
            const float2 f = __half22float2(hh);
            const int o0 = oh * 64 + w2 * 2;
            pl += f.x * swl[o0] + f.y * swl[o0 + 1];
            pr += f.x * swr[o0] + f.y * swr[o0 + 1];
        }
        pl += __shfl_xor_sync(0xffffffffu, pl, 1);
        pr += __shfl_xor_sync(0xffffffffu, pr, 1);
        if (oh == 0) {
            g_al[b * NN + j0 + r] = pl;
            g_ar[b * NN + j0 + r] = pr;
        }
    }
}

// ---------------------------------------------------------------------------
// Kernel 2 (main): fp16 mma + ldmatrix. CTA = 64 i x 128 o, grid 256, occ 2.
// Warp tile 16i x 64o. Double-buffered smem; LDG prefetch overlaps MMA.
// ---------------------------------------------------------------------------
#define SA_W 20                         // words per 32-half row (+pad)
#define SB_W 20
#define SA_TILE_W (64 * SA_W)           // 1280 words
#define SB_TILE_W (128 * SB_W)          // 2560 words
#define SA_TILE_B (SA_TILE_W * 4)
#define SB_TILE_B (SB_TILE_W * 4)
#define MAIN_SMEM_WORDS (2 * SA_TILE_W + 2 * SB_TILE_W + NN + 64)
#define MAIN_SMEM_BYTES (MAIN_SMEM_WORDS * 4)

__global__ void __launch_bounds__(256, 2)
fagcn_main(const int* __restrict__ adj, const float* __restrict__ x0,
           float* __restrict__ out) {
    extern __shared__ __align__(16) uint32_t smw[];
    uint32_t* sA  = smw;                          // [2][64 i][20]
    uint32_t* sB  = smw + 2 * SA_TILE_W;          // [2][128 o][20]
    float*    sAl = (float*)(smw + 2 * SA_TILE_W + 2 * SB_TILE_W);
    float*    sAr = sAl + NN;

    const int tid  = threadIdx.x;
    const int w    = tid >> 5;
    const int lane = tid & 31;
    const int fr   = lane >> 2;
    const int fc   = lane & 3;
    const int b    = blockIdx.x >> 5;
    const int i0   = (blockIdx.x & 31) * 64;

    // stage alpha_l (2048) and alpha_r (64)
    for (int i = tid; i < NN; i += 256) sAl[i] = g_al[b * NN + i];
    if (tid < 64) sAr[tid] = g_ar[b * NN + i0 + tid];
    __syncthreads();

    // A build mapping: jcol=(tid&7)*4, rows q*32 + (tid>>3), q<2
    const int jcol  = (tid & 7) * 4;
    const int ibase = tid >> 3;
    const int* adjp[2];
    float arv[2];
#pragma unroll
    for (int q = 0; q < 2; q++) {
        const int ia = q * 32 + ibase;
        adjp[q] = adj + ((size_t)(b * NN + i0 + ia)) * NN + jcol;
        arv[q] = sAr[ia];
    }
    const uint4* hTb = (const uint4*)(g_hT + ((size_t)b * 64 * 128) * 32);

    // warp tile: rows (w&3)*16, cols (w>>2)*64
    const int wm = (w & 3) * 16;
    const int wn = (w >> 2) * 64;

    // ldmatrix per-lane addresses
    const uint32_t sAb = smem_u32(sA);
    const uint32_t sBb = smem_u32(sB);
    const uint32_t aAddr = sAb + (uint32_t)(wm + (lane & 7) + 8 * ((lane >> 3) & 1)) * (SA_W * 4)
                         + (uint32_t)(lane >> 4) * 16;
    const uint32_t bAddr = sBb + (uint32_t)(wn + (lane & 7) + 8 * (lane >> 4)) * (SB_W * 4)
                         + (uint32_t)((lane >> 3) & 1) * 16;

    float acc[8][4];
#pragma unroll
    for (int nt = 0; nt < 8; nt++)
#pragma unroll
        for (int c = 0; c < 4; c++) acc[nt][c] = 0.0f;

    int4  padj[2];
    uint4 pB[2];

    // ---- prologue: fetch + build tile 0 into buffer 0 ----
#pragma unroll
    for (int q = 0; q < 2; q++) padj[q] = *(const int4*)adjp[q];
#pragma unroll
    for (int q = 0; q < 2; q++) pB[q] = hTb[(size_t)q * 256 + tid];
    {
        const float4 al4 = *(const float4*)&sAl[jcol];
#pragma unroll
        for (int q = 0; q < 2; q++) {
            const float t0 = padj[q].x ? tanh_fast(arv[q] * al4.x) : 0.0f;
            const float t1 = padj[q].y ? tanh_fast(arv[q] * al4.y) : 0.0f;
            const float t2 = padj[q].z ? tanh_fast(arv[q] * al4.z) : 0.0f;
            const float t3 = padj[q].w ? tanh_fast(arv[q] * al4.w) : 0.0f;
            uint2 p; p.x = f2h2(t0, t1); p.y = f2h2(t2, t3);
            *(uint2*)&sA[(q * 32 + ibase) * SA_W + (tid & 7) * 2] = p;
        }
#pragma unroll
        for (int q = 0; q < 2; q++) {
            const int idx = q * 256 + tid;
            *(uint4*)&sB[(idx >> 2) * SB_W + (idx & 3) * 4] = pB[q];
        }
    }
    __syncthreads();

    for (int kt = 0; kt < 64; kt++) {
        const int s = kt & 1;

        // prefetch next tile
        if (kt < 63) {
            const int j0n = (kt + 1) * 32;
#pragma unroll
            for (int q = 0; q < 2; q++) padj[q] = *(const int4*)(adjp[q] + j0n);
#pragma unroll
            for (int q = 0; q < 2; q++)
                pB[q] = hTb[(size_t)(kt + 1) * 512 + q * 256 + tid];
        }

        // ---- MMA over buffer s (ldmatrix fragments) ----
        {
            const uint32_t aA = aAddr + s * SA_TILE_B;
            const uint32_t bA = bAddr + s * SB_TILE_B;
#pragma unroll
            for (int ks = 0; ks < 2; ks++) {
                uint32_t af[4];
                ldmatrix_x4(af[0], af[1], af[2], af[3], aA + ks * 32);
#pragma unroll
                for (int np = 0; np < 4; np++) {
                    uint32_t b0, b1, b2, b3;
                    ldmatrix_x4(b0, b1, b2, b3, bA + np * (16 * SB_W * 4) + ks * 32);
                    mma_f16(acc[2 * np],     af, b0, b1);
                    mma_f16(acc[2 * np + 1], af, b2, b3);
                }
            }
        }

        // ---- build next tile into buffer s^1 ----
        if (kt < 63) {
            const int j0n = (kt + 1) * 32;
            uint32_t* An = sA + (s ^ 1) * SA_TILE_W;
            uint32_t* Bn = sB + (s ^ 1) * SB_TILE_W;
            const float4 al4 = *(const float4*)&sAl[j0n + jcol];
#pragma unroll
            for (int q = 0; q < 2; q++) {
                const float t0 = padj[q].x ? tanh_fast(arv[q] * al4.x) : 0.0f;
                const float t1 = padj[q].y ? tanh_fast(arv[q] * al4.y) : 0.0f;
                const float t2 = padj[q].z ? tanh_fast(arv[q] * al4.z) : 0.0f;
                const float t3 = padj[q].w ? tanh_fast(arv[q] * al4.w) : 0.0f;
                uint2 p; p.x = f2h2(t0, t1); p.y = f2h2(t2, t3);
                *(uint2*)&An[(q * 32 + ibase) * SA_W + (tid & 7) * 2] = p;
            }
#pragma unroll
            for (int q = 0; q < 2; q++) {
                const int idx = q * 256 + tid;
                *(uint4*)&Bn[(idx >> 2) * SB_W + (idx & 3) * 4] = pB[q];
            }
        }
        __syncthreads();
    }

    // ---- epilogue: out = acc + EPS * x0 ----
    {
        const int row = i0 + wm + fr;
#pragma unroll
        for (int nt = 0; nt < 8; nt++) {
            const int col = wn + nt * 8 + fc * 2;
            const size_t base0 = ((size_t)(b * NN + row)) * CC + col;
            const size_t base1 = base0 + 8 * CC;
            const float2 x00 = *(const float2*)&x0[base0];
            const float2 x01 = *(const float2*)&x0[base1];
            float2 o0, o1;
            o0.x = acc[nt][0] + EPSV * x00.x;
            o0.y = acc[nt][1] + EPSV * x00.y;
            o1.x = acc[nt][2] + EPSV * x01.x;
            o1.y = acc[nt][3] + EPSV * x01.y;
            *(float2*)&out[base0] = o0;
            *(float2*)&out[base1] = o1;
        }
    }
}

extern "C" void kernel_launch(void* const* d_in, const int* in_sizes, int n_in,
                              void* d_out, int out_size) {
    const float* x   = (const float*)d_in[0];
    const float* x0  = (const float*)d_in[1];
    const int*   adj = (const int*)d_in[2];
    const float* W   = (const float*)d_in[3];
    const float* wl  = (const float*)d_in[4];
    const float* wr  = (const float*)d_in[5];
    float* out = (float*)d_out;

    static bool attr_set = false;
    if (!attr_set) {
        cudaFuncSetAttribute(prep_tensor, cudaFuncAttributeMaxDynamicSharedMemorySize,
                             PREP_SMEM_BYTES);
        cudaFuncSetAttribute(fagcn_main, cudaFuncAttributeMaxDynamicSharedMemorySize,
                             MAIN_SMEM_BYTES);
        attr_set = true;
    }

    convW_kernel<<<16, 256>>>(W);
    prep_tensor<<<BATCH * (NN / 128), 256, PREP_SMEM_BYTES>>>(x, wl, wr);
    fagcn_main<<<BATCH * (NN / 64), 256, MAIN_SMEM_BYTES>>>(adj, x0, out);
}